// round 14
// baseline (speedup 1.0000x reference)
#include <cuda_runtime.h>
#include <math.h>

#define BS 32
#define NA 8400
#define NC 80
#define NB 64
#define TOPK 13
#define CAP 512
#define EPSF 1e-9f
#define IOU_EPS 1e-7f
#define GW 32
#define GH 32
#define BININV 0.05f   // 1/20 px
#define TOUCH_MAX (BS * NB * TOPK)

// ---------------- scratch ----------------
// g_s is fully zeroed each call by a cudaMemsetAsync graph node before k_init.
// ovkey encoding: (ov_bits<<32) | (63-j); zero = "no positive overlap seen".
struct Scratch {
    unsigned long long ovkey[BS * NA];
    unsigned pos_align[BS * NB];
    unsigned pos_over [BS * NB];
    int      bincnt[GW * GH];
    int      ntouch;
    int      done0;
};
__device__ Scratch g_s;

// INVARIANTS (zero at module load, restored by consumers each call):
//   g_cnt all-zero       (k_resolve resets touched entries)
//   g_assigned all-zero  (k_out resets touched entries; jm+1 encoding, 0 = background)
__device__ int                g_bin_start[GW * GH + 1];
__device__ int                g_abin[NA];
__device__ __align__(16) float4 g_bpack[NA];          // (x, y, id_bits, unused)
__device__ int                g_cnt     [BS * NA];
__device__ int                g_candj   [BS * NA];
__device__ float              g_met_a   [BS * NA];
__device__ float              g_ov_a    [BS * NA];
__device__ int                g_assigned[BS * NA];
__device__ float              g_norm_al [BS * NA];
__device__ int                g_touch[TOUCH_MAX];

__device__ __forceinline__ float pow6(float x) { float x2 = x * x; return x2 * x2 * x2; }

// CIoU with gt-side terms precomputed (area1 = w1*h1, atan1 = atanf(w1/h1))
__device__ __forceinline__ float ciou_pre(float gx1, float gy1, float gx2, float gy2,
                                          float area1, float atan1,
                                          float px1, float py1, float px2, float py2) {
    float w2 = px2 - px1, h2 = py2 - py1 + IOU_EPS;
    float iw = fminf(gx2, px2) - fmaxf(gx1, px1);
    float ih = fminf(gy2, py2) - fmaxf(gy1, py1);
    float inter = fmaxf(iw, 0.f) * fmaxf(ih, 0.f);
    float uni = area1 + w2 * h2 - inter + IOU_EPS;
    float iou = inter / uni;
    float cw = fmaxf(gx2, px2) - fminf(gx1, px1);
    float ch = fmaxf(gy2, py2) - fminf(gy1, py1);
    float c2 = cw * cw + ch * ch + IOU_EPS;
    float dx = px1 + px2 - gx1 - gx2;
    float dy = py1 + py2 - gy1 - gy2;
    float rho2 = (dx * dx + dy * dy) * 0.25f;
    float dat = atanf(w2 / h2) - atan1;
    float v = 0.4052847345693511f * dat * dat;
    float alpha = v / (v - iou + (1.0f + IOU_EPS));
    return iou - (rho2 / c2 + v * alpha);
}

// ---------------- kernel I: score-region zero + bin count + (last block) scan/scatter ----------------
// The 86 MB zero-fill rides the otherwise idle memory pipe of this
// latency-bound kernel; k_out later writes only the sparse one-hot entries.
__global__ void k_init(const float* __restrict__ anc, float* __restrict__ out) {
    const int tid = threadIdx.x;
    int gid = blockIdx.x * blockDim.x + tid;
    int stride = gridDim.x * blockDim.x;
    for (int i = gid; i < NA; i += stride) {
        float ax = anc[i * 2 + 0], ay = anc[i * 2 + 1];
        int bx = min(GW - 1, max(0, (int)(ax * BININV)));
        int by = min(GH - 1, max(0, (int)(ay * BININV)));
        int bin = by * GW + bx;
        g_abin[i] = bin;
        atomicAdd(&g_s.bincnt[bin], 1);   // zeroed by the memset node
    }

    // stream zeros over the target_scores region (write-once, consumed by k_out scatter)
    {
        const long long L = (long long)BS * NA;
        float4* s4 = (float4*)(out + L * 5);
        const int n4 = (int)(L * NC / 4);
        float4 z = make_float4(0.f, 0.f, 0.f, 0.f);
        for (int k = gid; k < n4; k += stride) __stcs(&s4[k], z);
    }

    // ---- last block does the bin scan + scatter ----
    __threadfence();
    __syncthreads();
    __shared__ int islast;
    if (tid == 0) islast = (atomicAdd(&g_s.done0, 1) == (int)gridDim.x - 1);
    __syncthreads();
    if (!islast) return;

    __shared__ int s[GW * GH];
    __shared__ int soff[GW * GH];
    int myc = g_s.bincnt[tid];
    s[tid] = myc;
    __syncthreads();
    for (int off = 1; off < GW * GH; off <<= 1) {
        int v = (tid >= off) ? s[tid - off] : 0;
        __syncthreads();
        s[tid] += v;
        __syncthreads();
    }
    g_bin_start[tid + 1] = s[tid];
    if (tid == 0) g_bin_start[0] = 0;
    soff[tid] = s[tid] - myc;           // exclusive
    __syncthreads();
    for (int i = tid; i < NA; i += GW * GH) {
        int bin = g_abin[i];
        int slot = atomicAdd(&soff[bin], 1);
        g_bpack[slot] = make_float4(anc[i * 2 + 0], anc[i * 2 + 1], __int_as_float(i), 0.f);
    }
}

// ---------------- kernel B: warp-per-row candidates + top-13 + zero-fill + scatter ----------------
#define ROWS_PER_BLOCK 4
__global__ void k_rows(const float* __restrict__ pd_scores, const float* __restrict__ pd_bboxes,
                       const float* __restrict__ anc, const int* __restrict__ gt_labels,
                       const float* __restrict__ gt_bboxes, const float* __restrict__ mask_gt) {
    const int wid = threadIdx.x >> 5;
    const int lane = threadIdx.x & 31;
    const int row = blockIdx.x * ROWS_PER_BLOCK + wid;   // b*NB + j

    __shared__ unsigned long long skey[ROWS_PER_BLOCK][CAP];
    __shared__ float sov[ROWS_PER_BLOCK][CAP];
    __shared__ int sP[ROWS_PER_BLOCK];
    __shared__ int sfidx[ROWS_PER_BLOCK][TOPK];
    __shared__ float sfmet[ROWS_PER_BLOCK][TOPK];
    __shared__ float sfovl[ROWS_PER_BLOCK][TOPK];

    if (row >= BS * NB) return;
    if (mask_gt[row] <= 0.f) return;
    const int b = row >> 6, j = row & 63;

    if (lane == 0) sP[wid] = 0;
    __syncwarp();

    const float gx1 = gt_bboxes[row * 4 + 0], gy1 = gt_bboxes[row * 4 + 1];
    const float gx2 = gt_bboxes[row * 4 + 2], gy2 = gt_bboxes[row * 4 + 3];
    const int lbl = gt_labels[row];
    const float w1 = gx2 - gx1, h1 = gy2 - gy1 + IOU_EPS;
    const float area1 = w1 * h1;
    const float atan1 = atanf(w1 / h1);
    const unsigned jpack = (unsigned)(NB - 1 - j);

    int bx_lo = min(GW - 1, max(0, (int)floorf(gx1 * BININV)));
    int bx_hi = min(GW - 1, max(0, (int)floorf(gx2 * BININV)));
    int by_lo = min(GH - 1, max(0, (int)floorf(gy1 * BININV)));
    int by_hi = min(GH - 1, max(0, (int)floorf(gy2 * BININV)));

    for (int by = by_lo; by <= by_hi; by++) {
        int s = g_bin_start[by * GW + bx_lo];
        int e = g_bin_start[by * GW + bx_hi + 1];
        for (int i = s + lane; i < e; i += 32) {
            const float4 p = g_bpack[i];
            float ax = p.x, ay = p.y;
            if (!(ax - gx1 > EPSF && ay - gy1 > EPSF && gx2 - ax > EPSF && gy2 - ay > EPSF)) continue;
            int a = __float_as_int(p.z);
            int apos = b * NA + a;
            const float4 pb = __ldg((const float4*)(pd_bboxes + (long long)apos * 4));
            float ov = fmaxf(ciou_pre(gx1, gy1, gx2, gy2, area1, atan1, pb.x, pb.y, pb.z, pb.w), 0.f);
            if (ov > 0.f) {
                // feed the global overlaps-argmax (max ov, first-max/smallest-j tie-break)
                atomicMax(&g_s.ovkey[apos],
                          ((unsigned long long)__float_as_uint(ov) << 32) | jpack);
                float met = __ldg(pd_scores + (long long)apos * NC + lbl) * pow6(ov);
                if (met > 0.f) {
                    int slot = atomicAdd(&sP[wid], 1);
                    if (slot < CAP) {
                        skey[wid][slot] = ((unsigned long long)__float_as_uint(met) << 32)
                                        | (unsigned)(0xFFFFFFFFu - (unsigned)a);
                        sov[wid][slot] = ov;
                    }
                }
            }
        }
    }
    __syncwarp();
    int P = min(sP[wid], CAP);
    int nsel = min(P, TOPK);

    // warp-only top-k: 13 rounds of shfl max-reduction, no block barriers
    for (int r = 0; r < nsel; r++) {
        unsigned long long best = 0; int bslot = -1;
        for (int i = lane; i < P; i += 32)
            if (skey[wid][i] > best) { best = skey[wid][i]; bslot = i; }
        #pragma unroll
        for (int off = 16; off > 0; off >>= 1) {
            unsigned long long ob = __shfl_down_sync(0xFFFFFFFFu, best, off);
            int os = __shfl_down_sync(0xFFFFFFFFu, bslot, off);
            if (ob > best) { best = ob; bslot = os; }
        }
        if (lane == 0) {
            sfidx[wid][r] = (int)(0xFFFFFFFFu - (unsigned)(best & 0xFFFFFFFFull));
            sfmet[wid][r] = __uint_as_float((unsigned)(best >> 32));
            sfovl[wid][r] = sov[wid][bslot];
            skey[wid][bslot] = 0ull;
        }
        __syncwarp();
    }

    int kfill = nsel;
    if (nsel < TOPK) {
        if (lane == 0) {
            // top_k fills remaining slots with smallest-index zero-metric anchors;
            // they survive only if inside the gt box.
            int slots = nsel;
            int a = 0;
            while (slots < TOPK && a < NA) {
                bool ispos = false;
                for (int t = 0; t < nsel; t++)
                    if (sfidx[wid][t] == a) { ispos = true; break; }
                if (!ispos) {
                    slots++;
                    float ax = anc[a * 2 + 0], ay = anc[a * 2 + 1];
                    if (ax - gx1 > EPSF && ay - gy1 > EPSF && gx2 - ax > EPSF && gy2 - ay > EPSF) {
                        sfidx[wid][kfill] = a; sfmet[wid][kfill] = 0.f; sfovl[wid][kfill] = 0.f;
                        kfill++;
                    }
                }
                a++;
            }
        }
        kfill = __shfl_sync(0xFFFFFFFFu, kfill, 0);
    }
    __syncwarp();

    if (lane < kfill) {
        int a = sfidx[wid][lane];
        int pos = b * NA + a;
        int old = atomicAdd(&g_cnt[pos], 1);
        if (old == 0) {
            int t = atomicAdd(&g_s.ntouch, 1);
            g_touch[t] = pos;
        }
        g_candj[pos] = j;            // race only matters when cnt>1 (value unused then)
        g_met_a[pos] = sfmet[wid][lane];
        g_ov_a[pos]  = sfovl[wid][lane];
    }
}

// ---------------- kernel C: per-touched-anchor resolution + pos maxima (+ cnt reset) ----------------
__global__ void k_resolve(const float* __restrict__ pd_scores, const int* __restrict__ gt_labels) {
    int i = blockIdx.x * blockDim.x + threadIdx.x;
    if (i >= g_s.ntouch) return;
    int pos = g_touch[i];
    int c = g_cnt[pos];
    g_cnt[pos] = 0;                  // restore all-zero invariant (touched-only dirty)
    int b = pos / NA;
    int jm; float met, ov;
    if (c == 1) {
        jm = g_candj[pos]; met = g_met_a[pos]; ov = g_ov_a[pos];
    } else {
        // overlaps argmax precomputed during the candidate scan
        unsigned long long key = g_s.ovkey[pos];
        if (key == 0ull) {           // no gt had ov>0 for this anchor: argmax of zero row = 0
            jm = 0; ov = 0.f;
        } else {
            jm = NB - 1 - (int)(key & 0xFFFFFFFFull);
            ov = __uint_as_float((unsigned)(key >> 32));
        }
        met = (ov > 0.f)
            ? __ldg(pd_scores + (long long)pos * NC + __ldg(gt_labels + b * NB + jm)) * pow6(ov)
            : 0.f;
    }
    g_assigned[pos] = jm + 1;        // 0 = background encoding
    g_norm_al[pos]  = met;
    atomicMax(&g_s.pos_align[b * NB + jm], __float_as_uint(met));
    atomicMax(&g_s.pos_over [b * NB + jm], __float_as_uint(ov));
}

// ---------------- kernel D: metadata outputs + sparse one-hot (scores pre-zeroed by k_init) ----------------
__global__ void k_out(const int* __restrict__ gt_labels, const float* __restrict__ gt_bboxes,
                      float* __restrict__ out) {
    int b = blockIdx.y;
    int a = blockIdx.x * blockDim.x + threadIdx.x;
    if (a >= NA) return;
    const long long L = (long long)BS * NA;
    long long pos = (long long)b * NA + a;
    int v = g_assigned[pos];
    bool fg = (v > 0);
    if (fg) g_assigned[pos] = 0;     // restore all-zero invariant (touched-only dirty)
    int jm = v - 1;
    int j0 = fg ? jm : 0;
    int label = gt_labels[b * NB + j0];
    const float4 gb = *(const float4*)(gt_bboxes + (b * NB + j0) * 4);
    out[pos] = (float)label;
    *(float4*)(out + L + pos * 4) = gb;
    out[L * 5 + L * NC + pos] = fg ? 1.f : 0.f;
    out[L * 6 + L * NC + pos] = (float)j0;
    if (fg) {
        float pa = __uint_as_float(g_s.pos_align[b * NB + jm]);
        float po = __uint_as_float(g_s.pos_over [b * NB + jm]);
        out[L * 5 + pos * NC + label] = g_norm_al[pos] * po / (pa + EPSF);
    }
}

// ---------------- launch ----------------
extern "C" void kernel_launch(void* const* d_in, const int* in_sizes, int n_in,
                              void* d_out, int out_size) {
    const float* pd_scores = (const float*)d_in[0];
    const float* pd_bboxes = (const float*)d_in[1];
    const float* anc       = (const float*)d_in[2];
    const int*   gt_labels = (const int*)  d_in[3];
    const float* gt_bboxes = (const float*)d_in[4];
    const float* mask_gt   = (const float*)d_in[5];
    float* out = (float*)d_out;

    // zero all per-call scratch in one small memset node
    void* sptr = nullptr;
    cudaGetSymbolAddress(&sptr, g_s);
    cudaMemsetAsync(sptr, 0, sizeof(Scratch), 0);

    k_init<<<264, 1024>>>(anc, out);
    k_rows<<<(BS * NB) / ROWS_PER_BLOCK, 32 * ROWS_PER_BLOCK>>>(pd_scores, pd_bboxes, anc, gt_labels, gt_bboxes, mask_gt);
    k_resolve<<<(TOUCH_MAX + 255) / 256, 256>>>(pd_scores, gt_labels);
    dim3 gridD((NA + 255) / 256, BS);
    k_out<<<gridD, 256>>>(gt_labels, gt_bboxes, out);
}

// round 15
// speedup vs baseline: 1.0006x; 1.0006x over previous
#include <cuda_runtime.h>
#include <math.h>

#define BS 32
#define NA 8400
#define NC 80
#define NB 64
#define TOPK 13
#define CAP 512
#define EPSF 1e-9f
#define IOU_EPS 1e-7f
#define GW 32
#define GH 32
#define BININV 0.05f   // 1/20 px
#define TOUCH_MAX (BS * NB * TOPK)
#define RB_GRID ((BS * NB) / 4)

// ---------------- scratch ----------------
// g_s is fully zeroed each call by a cudaMemsetAsync graph node before k_init.
// ovkey encoding: (ov_bits<<32) | (63-j); zero = "no positive overlap seen".
struct Scratch {
    unsigned long long ovkey[BS * NA];
    unsigned pos_align[BS * NB];
    unsigned pos_over [BS * NB];
    int      bincnt[GW * GH];
    int      ntouch;
    int      done0;
};
__device__ Scratch g_s;

// INVARIANTS (zero at module load, restored by consumers each call):
//   g_cnt all-zero       (k_resolve resets touched entries)
//   g_assigned all-zero  (k_out resets touched entries; jm+1 encoding, 0 = background)
__device__ int                g_bin_start[GW * GH + 1];
__device__ int                g_abin[NA];
__device__ __align__(16) float4 g_bpack[NA];          // (x, y, id_bits, unused)
__device__ int                g_cnt     [BS * NA];
__device__ int                g_candj   [BS * NA];
__device__ float              g_met_a   [BS * NA];
__device__ float              g_ov_a    [BS * NA];
__device__ int                g_assigned[BS * NA];
__device__ float              g_norm_al [BS * NA];
__device__ int                g_touch[TOUCH_MAX];

__device__ __forceinline__ float pow6(float x) { float x2 = x * x; return x2 * x2 * x2; }

// CIoU with gt-side terms precomputed (area1 = w1*h1, atan1 = atanf(w1/h1))
__device__ __forceinline__ float ciou_pre(float gx1, float gy1, float gx2, float gy2,
                                          float area1, float atan1,
                                          float px1, float py1, float px2, float py2) {
    float w2 = px2 - px1, h2 = py2 - py1 + IOU_EPS;
    float iw = fminf(gx2, px2) - fmaxf(gx1, px1);
    float ih = fminf(gy2, py2) - fmaxf(gy1, py1);
    float inter = fmaxf(iw, 0.f) * fmaxf(ih, 0.f);
    float uni = area1 + w2 * h2 - inter + IOU_EPS;
    float iou = inter / uni;
    float cw = fmaxf(gx2, px2) - fminf(gx1, px1);
    float ch = fmaxf(gy2, py2) - fminf(gy1, py1);
    float c2 = cw * cw + ch * ch + IOU_EPS;
    float dx = px1 + px2 - gx1 - gx2;
    float dy = py1 + py2 - gy1 - gy2;
    float rho2 = (dx * dx + dy * dy) * 0.25f;
    float dat = atanf(w2 / h2) - atan1;
    float v = 0.4052847345693511f * dat * dat;
    float alpha = v / (v - iou + (1.0f + IOU_EPS));
    return iou - (rho2 / c2 + v * alpha);
}

// ---------------- kernel I: bin count + (last block) scan/scatter ----------------
__global__ void k_init(const float* __restrict__ anc) {
    const int tid = threadIdx.x;
    int gid = blockIdx.x * blockDim.x + tid;
    int stride = gridDim.x * blockDim.x;
    for (int i = gid; i < NA; i += stride) {
        float ax = anc[i * 2 + 0], ay = anc[i * 2 + 1];
        int bx = min(GW - 1, max(0, (int)(ax * BININV)));
        int by = min(GH - 1, max(0, (int)(ay * BININV)));
        int bin = by * GW + bx;
        g_abin[i] = bin;
        atomicAdd(&g_s.bincnt[bin], 1);   // zeroed by the memset node
    }

    // ---- last block does the bin scan + scatter ----
    __threadfence();
    __syncthreads();
    __shared__ int islast;
    if (tid == 0) islast = (atomicAdd(&g_s.done0, 1) == (int)gridDim.x - 1);
    __syncthreads();
    if (!islast) return;

    __shared__ int s[GW * GH];
    __shared__ int soff[GW * GH];
    int myc = g_s.bincnt[tid];
    s[tid] = myc;
    __syncthreads();
    for (int off = 1; off < GW * GH; off <<= 1) {
        int v = (tid >= off) ? s[tid - off] : 0;
        __syncthreads();
        s[tid] += v;
        __syncthreads();
    }
    g_bin_start[tid + 1] = s[tid];
    if (tid == 0) g_bin_start[0] = 0;
    soff[tid] = s[tid] - myc;           // exclusive
    __syncthreads();
    for (int i = tid; i < NA; i += GW * GH) {
        int bin = g_abin[i];
        int slot = atomicAdd(&soff[bin], 1);
        g_bpack[slot] = make_float4(anc[i * 2 + 0], anc[i * 2 + 1], __int_as_float(i), 0.f);
    }
}

// ---------------- kernel B: score zero-fill + warp-per-row candidates + top-13 + scatter ----------------
// The 86 MB target_scores zero-fill is interleaved here: it is independent
// streaming-store work that rides the idle memory pipe of this latency-bound
// kernel. k_out (2 launches later) only adds the sparse one-hot entries.
#define ROWS_PER_BLOCK 4
__global__ void k_rows(const float* __restrict__ pd_scores, const float* __restrict__ pd_bboxes,
                       const float* __restrict__ anc, const int* __restrict__ gt_labels,
                       const float* __restrict__ gt_bboxes, const float* __restrict__ mask_gt,
                       float* __restrict__ out) {
    const int wid = threadIdx.x >> 5;
    const int lane = threadIdx.x & 31;
    const int row = blockIdx.x * ROWS_PER_BLOCK + wid;   // b*NB + j

    __shared__ unsigned long long skey[ROWS_PER_BLOCK][CAP];
    __shared__ float sov[ROWS_PER_BLOCK][CAP];
    __shared__ int sP[ROWS_PER_BLOCK];
    __shared__ int sfidx[ROWS_PER_BLOCK][TOPK];
    __shared__ float sfmet[ROWS_PER_BLOCK][TOPK];
    __shared__ float sfovl[ROWS_PER_BLOCK][TOPK];

    // ---- phase 0: stream zeros over this block's slice of target_scores ----
    {
        const long long L = (long long)BS * NA;
        float4* s4 = (float4*)(out + L * 5);
        const int n4 = (int)(L * NC / 4);                 // 5,376,000 float4
        int gid = blockIdx.x * blockDim.x + threadIdx.x;
        int stride = RB_GRID * blockDim.x;                // 65,536
        float4 z = make_float4(0.f, 0.f, 0.f, 0.f);
        for (int k = gid; k < n4; k += stride) __stcs(&s4[k], z);
    }

    if (row >= BS * NB) return;
    if (mask_gt[row] <= 0.f) return;
    const int b = row >> 6, j = row & 63;

    if (lane == 0) sP[wid] = 0;
    __syncwarp();

    const float gx1 = gt_bboxes[row * 4 + 0], gy1 = gt_bboxes[row * 4 + 1];
    const float gx2 = gt_bboxes[row * 4 + 2], gy2 = gt_bboxes[row * 4 + 3];
    const int lbl = gt_labels[row];
    const float w1 = gx2 - gx1, h1 = gy2 - gy1 + IOU_EPS;
    const float area1 = w1 * h1;
    const float atan1 = atanf(w1 / h1);
    const unsigned jpack = (unsigned)(NB - 1 - j);

    int bx_lo = min(GW - 1, max(0, (int)floorf(gx1 * BININV)));
    int bx_hi = min(GW - 1, max(0, (int)floorf(gx2 * BININV)));
    int by_lo = min(GH - 1, max(0, (int)floorf(gy1 * BININV)));
    int by_hi = min(GH - 1, max(0, (int)floorf(gy2 * BININV)));

    for (int by = by_lo; by <= by_hi; by++) {
        int s = g_bin_start[by * GW + bx_lo];
        int e = g_bin_start[by * GW + bx_hi + 1];
        for (int i = s + lane; i < e; i += 32) {
            const float4 p = g_bpack[i];
            float ax = p.x, ay = p.y;
            if (!(ax - gx1 > EPSF && ay - gy1 > EPSF && gx2 - ax > EPSF && gy2 - ay > EPSF)) continue;
            int a = __float_as_int(p.z);
            int apos = b * NA + a;
            const float4 pb = __ldg((const float4*)(pd_bboxes + (long long)apos * 4));
            float ov = fmaxf(ciou_pre(gx1, gy1, gx2, gy2, area1, atan1, pb.x, pb.y, pb.z, pb.w), 0.f);
            if (ov > 0.f) {
                // feed the global overlaps-argmax (max ov, first-max/smallest-j tie-break)
                atomicMax(&g_s.ovkey[apos],
                          ((unsigned long long)__float_as_uint(ov) << 32) | jpack);
                float met = __ldg(pd_scores + (long long)apos * NC + lbl) * pow6(ov);
                if (met > 0.f) {
                    int slot = atomicAdd(&sP[wid], 1);
                    if (slot < CAP) {
                        skey[wid][slot] = ((unsigned long long)__float_as_uint(met) << 32)
                                        | (unsigned)(0xFFFFFFFFu - (unsigned)a);
                        sov[wid][slot] = ov;
                    }
                }
            }
        }
    }
    __syncwarp();
    int P = min(sP[wid], CAP);
    int nsel = min(P, TOPK);

    // warp-only top-k: 13 rounds of shfl max-reduction, no block barriers
    for (int r = 0; r < nsel; r++) {
        unsigned long long best = 0; int bslot = -1;
        for (int i = lane; i < P; i += 32)
            if (skey[wid][i] > best) { best = skey[wid][i]; bslot = i; }
        #pragma unroll
        for (int off = 16; off > 0; off >>= 1) {
            unsigned long long ob = __shfl_down_sync(0xFFFFFFFFu, best, off);
            int os = __shfl_down_sync(0xFFFFFFFFu, bslot, off);
            if (ob > best) { best = ob; bslot = os; }
        }
        if (lane == 0) {
            sfidx[wid][r] = (int)(0xFFFFFFFFu - (unsigned)(best & 0xFFFFFFFFull));
            sfmet[wid][r] = __uint_as_float((unsigned)(best >> 32));
            sfovl[wid][r] = sov[wid][bslot];
            skey[wid][bslot] = 0ull;
        }
        __syncwarp();
    }

    int kfill = nsel;
    if (nsel < TOPK) {
        if (lane == 0) {
            // top_k fills remaining slots with smallest-index zero-metric anchors;
            // they survive only if inside the gt box.
            int slots = nsel;
            int a = 0;
            while (slots < TOPK && a < NA) {
                bool ispos = false;
                for (int t = 0; t < nsel; t++)
                    if (sfidx[wid][t] == a) { ispos = true; break; }
                if (!ispos) {
                    slots++;
                    float ax = anc[a * 2 + 0], ay = anc[a * 2 + 1];
                    if (ax - gx1 > EPSF && ay - gy1 > EPSF && gx2 - ax > EPSF && gy2 - ay > EPSF) {
                        sfidx[wid][kfill] = a; sfmet[wid][kfill] = 0.f; sfovl[wid][kfill] = 0.f;
                        kfill++;
                    }
                }
                a++;
            }
        }
        kfill = __shfl_sync(0xFFFFFFFFu, kfill, 0);
    }
    __syncwarp();

    if (lane < kfill) {
        int a = sfidx[wid][lane];
        int pos = b * NA + a;
        int old = atomicAdd(&g_cnt[pos], 1);
        if (old == 0) {
            int t = atomicAdd(&g_s.ntouch, 1);
            g_touch[t] = pos;
        }
        g_candj[pos] = j;            // race only matters when cnt>1 (value unused then)
        g_met_a[pos] = sfmet[wid][lane];
        g_ov_a[pos]  = sfovl[wid][lane];
    }
}

// ---------------- kernel C: per-touched-anchor resolution + pos maxima (+ cnt reset) ----------------
__global__ void k_resolve(const float* __restrict__ pd_scores, const int* __restrict__ gt_labels) {
    int i = blockIdx.x * blockDim.x + threadIdx.x;
    if (i >= g_s.ntouch) return;
    int pos = g_touch[i];
    int c = g_cnt[pos];
    g_cnt[pos] = 0;                  // restore all-zero invariant (touched-only dirty)
    int b = pos / NA;
    int jm; float met, ov;
    if (c == 1) {
        jm = g_candj[pos]; met = g_met_a[pos]; ov = g_ov_a[pos];
    } else {
        // overlaps argmax precomputed during the candidate scan
        unsigned long long key = g_s.ovkey[pos];
        if (key == 0ull) {           // no gt had ov>0 for this anchor: argmax of zero row = 0
            jm = 0; ov = 0.f;
        } else {
            jm = NB - 1 - (int)(key & 0xFFFFFFFFull);
            ov = __uint_as_float((unsigned)(key >> 32));
        }
        met = (ov > 0.f)
            ? __ldg(pd_scores + (long long)pos * NC + __ldg(gt_labels + b * NB + jm)) * pow6(ov)
            : 0.f;
    }
    g_assigned[pos] = jm + 1;        // 0 = background encoding
    g_norm_al[pos]  = met;
    atomicMax(&g_s.pos_align[b * NB + jm], __float_as_uint(met));
    atomicMax(&g_s.pos_over [b * NB + jm], __float_as_uint(ov));
}

// ---------------- kernel D: metadata outputs + sparse one-hot (scores pre-zeroed by k_rows) ----------------
__global__ void k_out(const int* __restrict__ gt_labels, const float* __restrict__ gt_bboxes,
                      float* __restrict__ out) {
    int b = blockIdx.y;
    int a = blockIdx.x * blockDim.x + threadIdx.x;
    if (a >= NA) return;
    const long long L = (long long)BS * NA;
    long long pos = (long long)b * NA + a;
    int v = g_assigned[pos];
    bool fg = (v > 0);
    if (fg) g_assigned[pos] = 0;     // restore all-zero invariant (touched-only dirty)
    int jm = v - 1;
    int j0 = fg ? jm : 0;
    int label = gt_labels[b * NB + j0];
    const float4 gb = *(const float4*)(gt_bboxes + (b * NB + j0) * 4);
    out[pos] = (float)label;
    *(float4*)(out + L + pos * 4) = gb;
    out[L * 5 + L * NC + pos] = fg ? 1.f : 0.f;
    out[L * 6 + L * NC + pos] = (float)j0;
    if (fg) {
        float pa = __uint_as_float(g_s.pos_align[b * NB + jm]);
        float po = __uint_as_float(g_s.pos_over [b * NB + jm]);
        out[L * 5 + pos * NC + label] = g_norm_al[pos] * po / (pa + EPSF);
    }
}

// ---------------- launch ----------------
extern "C" void kernel_launch(void* const* d_in, const int* in_sizes, int n_in,
                              void* d_out, int out_size) {
    const float* pd_scores = (const float*)d_in[0];
    const float* pd_bboxes = (const float*)d_in[1];
    const float* anc       = (const float*)d_in[2];
    const int*   gt_labels = (const int*)  d_in[3];
    const float* gt_bboxes = (const float*)d_in[4];
    const float* mask_gt   = (const float*)d_in[5];
    float* out = (float*)d_out;

    // zero all per-call scratch in one small memset node
    void* sptr = nullptr;
    cudaGetSymbolAddress(&sptr, g_s);
    cudaMemsetAsync(sptr, 0, sizeof(Scratch), 0);

    k_init<<<264, 1024>>>(anc);
    k_rows<<<RB_GRID, 32 * ROWS_PER_BLOCK>>>(pd_scores, pd_bboxes, anc, gt_labels, gt_bboxes, mask_gt, out);
    k_resolve<<<(TOUCH_MAX + 255) / 256, 256>>>(pd_scores, gt_labels);
    dim3 gridD((NA + 255) / 256, BS);
    k_out<<<gridD, 256>>>(gt_labels, gt_bboxes, out);
}

// round 16
// speedup vs baseline: 1.0842x; 1.0835x over previous
#include <cuda_runtime.h>
#include <math.h>

#define BS 32
#define NA 8400
#define NC 80
#define NB 64
#define TOPK 13
#define CAP 512
#define EPSF 1e-9f
#define IOU_EPS 1e-7f
#define GW 32
#define GH 32
#define BININV 0.05f   // 1/20 px
#define TOUCH_MAX (BS * NB * TOPK)
#define RB_GRID ((BS * NB) / 4)     // 512 row blocks
#define FILL_GRID 256               // dedicated zero-fill blocks (co-resident)

// ---------------- scratch ----------------
// ovkey encoding: (ov_bits<<32) | (63-j); zero = "no positive overlap seen".
struct Scratch {
    unsigned long long ovkey[BS * NA];
    unsigned pos_align[BS * NB];
    unsigned pos_over [BS * NB];
    int      bincnt[GW * GH];
    int      ntouch;
    int      done0;
};
__device__ Scratch g_s;

// INVARIANTS at entry to every kernel_launch call (zero at module load,
// restored by consumers each call):
//   g_s.bincnt all-zero, g_s.done0 == 0  (k_init last block restores)
//   g_cnt all-zero                        (k_resolve resets touched entries)
//   g_assigned all-zero                   (k_out resets touched entries; jm+1, 0 = background)
__device__ int                g_bin_start[GW * GH + 1];
__device__ int                g_abin[NA];
__device__ __align__(16) float4 g_bpack[NA];          // (x, y, id_bits, unused)
__device__ int                g_cnt     [BS * NA];
__device__ int                g_candj   [BS * NA];
__device__ float              g_met_a   [BS * NA];
__device__ float              g_ov_a    [BS * NA];
__device__ int                g_assigned[BS * NA];
__device__ float              g_norm_al [BS * NA];
__device__ int                g_touch[TOUCH_MAX];

__device__ __forceinline__ float pow6(float x) { float x2 = x * x; return x2 * x2 * x2; }

// CIoU with gt-side terms precomputed (area1 = w1*h1, atan1 = atanf(w1/h1))
__device__ __forceinline__ float ciou_pre(float gx1, float gy1, float gx2, float gy2,
                                          float area1, float atan1,
                                          float px1, float py1, float px2, float py2) {
    float w2 = px2 - px1, h2 = py2 - py1 + IOU_EPS;
    float iw = fminf(gx2, px2) - fmaxf(gx1, px1);
    float ih = fminf(gy2, py2) - fmaxf(gy1, py1);
    float inter = fmaxf(iw, 0.f) * fmaxf(ih, 0.f);
    float uni = area1 + w2 * h2 - inter + IOU_EPS;
    float iou = inter / uni;
    float cw = fmaxf(gx2, px2) - fminf(gx1, px1);
    float ch = fmaxf(gy2, py2) - fminf(gy1, py1);
    float c2 = cw * cw + ch * ch + IOU_EPS;
    float dx = px1 + px2 - gx1 - gx2;
    float dy = py1 + py2 - gy1 - gy2;
    float rho2 = (dx * dx + dy * dy) * 0.25f;
    float dat = atanf(w2 / h2) - atan1;
    float v = 0.4052847345693511f * dat * dat;
    float alpha = v / (v - iou + (1.0f + IOU_EPS));
    return iou - (rho2 / c2 + v * alpha);
}

// ---------------- kernel I: scratch zero + bin count + (last block) scan/scatter ----------------
__global__ void k_init(const float* __restrict__ anc) {
    const int tid = threadIdx.x;
    int gid = blockIdx.x * blockDim.x + tid;
    int stride = gridDim.x * blockDim.x;
    if (gid == 0) g_s.ntouch = 0;
    for (int i = gid; i < NA; i += stride) {
        float ax = anc[i * 2 + 0], ay = anc[i * 2 + 1];
        int bx = min(GW - 1, max(0, (int)(ax * BININV)));
        int by = min(GH - 1, max(0, (int)(ay * BININV)));
        int bin = by * GW + bx;
        g_abin[i] = bin;
        atomicAdd(&g_s.bincnt[bin], 1);   // zero at entry (invariant)
    }
    // zero ovkey + pos maxima (nothing reads them until k_rows / k_resolve)
    {
        ulonglong2* o2 = (ulonglong2*)g_s.ovkey;
        const int n2 = BS * NA / 2;
        ulonglong2 z2 = make_ulonglong2(0ull, 0ull);
        for (int k = gid; k < n2; k += stride) o2[k] = z2;
        for (int k = gid; k < BS * NB; k += stride) { g_s.pos_align[k] = 0u; g_s.pos_over[k] = 0u; }
    }

    // ---- last block does the bin scan + scatter ----
    __threadfence();
    __syncthreads();
    __shared__ int islast;
    if (tid == 0) islast = (atomicAdd(&g_s.done0, 1) == (int)gridDim.x - 1);
    __syncthreads();
    if (!islast) return;
    if (tid == 0) g_s.done0 = 0;        // restore invariant

    __shared__ int s[GW * GH];
    __shared__ int soff[GW * GH];
    int myc = g_s.bincnt[tid];
    g_s.bincnt[tid] = 0;                // restore invariant
    s[tid] = myc;
    __syncthreads();
    for (int off = 1; off < GW * GH; off <<= 1) {
        int v = (tid >= off) ? s[tid - off] : 0;
        __syncthreads();
        s[tid] += v;
        __syncthreads();
    }
    g_bin_start[tid + 1] = s[tid];
    if (tid == 0) g_bin_start[0] = 0;
    soff[tid] = s[tid] - myc;           // exclusive
    __syncthreads();
    for (int i = tid; i < NA; i += GW * GH) {
        int bin = g_abin[i];
        int slot = atomicAdd(&soff[bin], 1);
        g_bpack[slot] = make_float4(anc[i * 2 + 0], anc[i * 2 + 1], __int_as_float(i), 0.f);
    }
}

// ---------------- kernel B: heterogeneous grid ----------------
// blocks [0, RB_GRID):      warp-per-row candidates + top-13 + scatter (latency-bound)
// blocks [RB_GRID, +FILL):  stream zeros over target_scores (bandwidth-bound)
// Both kinds are co-resident -> the fill's DRAM traffic overlaps the scan's
// latency stalls instead of serializing before/after it.
#define ROWS_PER_BLOCK 4
__global__ void k_rows(const float* __restrict__ pd_scores, const float* __restrict__ pd_bboxes,
                       const float* __restrict__ anc, const int* __restrict__ gt_labels,
                       const float* __restrict__ gt_bboxes, const float* __restrict__ mask_gt,
                       float* __restrict__ out) {
    const int wid = threadIdx.x >> 5;
    const int lane = threadIdx.x & 31;

    if (blockIdx.x >= RB_GRID) {
        // ---- dedicated fill block ----
        const long long L = (long long)BS * NA;
        float4* s4 = (float4*)(out + L * 5);
        const int n4 = (int)(L * NC / 4);                 // 5,376,000 float4
        int gid = (blockIdx.x - RB_GRID) * blockDim.x + threadIdx.x;
        int stride = FILL_GRID * blockDim.x;
        float4 z = make_float4(0.f, 0.f, 0.f, 0.f);
        for (int k = gid; k < n4; k += stride) __stcs(&s4[k], z);
        return;
    }

    const int row = blockIdx.x * ROWS_PER_BLOCK + wid;   // b*NB + j

    __shared__ unsigned long long skey[ROWS_PER_BLOCK][CAP];
    __shared__ float sov[ROWS_PER_BLOCK][CAP];
    __shared__ int sP[ROWS_PER_BLOCK];
    __shared__ int sfidx[ROWS_PER_BLOCK][TOPK];
    __shared__ float sfmet[ROWS_PER_BLOCK][TOPK];
    __shared__ float sfovl[ROWS_PER_BLOCK][TOPK];

    if (row >= BS * NB) return;
    if (mask_gt[row] <= 0.f) return;
    const int b = row >> 6, j = row & 63;

    if (lane == 0) sP[wid] = 0;
    __syncwarp();

    const float gx1 = gt_bboxes[row * 4 + 0], gy1 = gt_bboxes[row * 4 + 1];
    const float gx2 = gt_bboxes[row * 4 + 2], gy2 = gt_bboxes[row * 4 + 3];
    const int lbl = gt_labels[row];
    const float w1 = gx2 - gx1, h1 = gy2 - gy1 + IOU_EPS;
    const float area1 = w1 * h1;
    const float atan1 = atanf(w1 / h1);
    const unsigned jpack = (unsigned)(NB - 1 - j);

    int bx_lo = min(GW - 1, max(0, (int)floorf(gx1 * BININV)));
    int bx_hi = min(GW - 1, max(0, (int)floorf(gx2 * BININV)));
    int by_lo = min(GH - 1, max(0, (int)floorf(gy1 * BININV)));
    int by_hi = min(GH - 1, max(0, (int)floorf(gy2 * BININV)));

    for (int by = by_lo; by <= by_hi; by++) {
        int s = g_bin_start[by * GW + bx_lo];
        int e = g_bin_start[by * GW + bx_hi + 1];
        for (int i = s + lane; i < e; i += 32) {
            const float4 p = g_bpack[i];
            float ax = p.x, ay = p.y;
            if (!(ax - gx1 > EPSF && ay - gy1 > EPSF && gx2 - ax > EPSF && gy2 - ay > EPSF)) continue;
            int a = __float_as_int(p.z);
            int apos = b * NA + a;
            const float4 pb = __ldg((const float4*)(pd_bboxes + (long long)apos * 4));
            float ov = fmaxf(ciou_pre(gx1, gy1, gx2, gy2, area1, atan1, pb.x, pb.y, pb.z, pb.w), 0.f);
            if (ov > 0.f) {
                // feed the global overlaps-argmax (max ov, first-max/smallest-j tie-break)
                atomicMax(&g_s.ovkey[apos],
                          ((unsigned long long)__float_as_uint(ov) << 32) | jpack);
                float met = __ldg(pd_scores + (long long)apos * NC + lbl) * pow6(ov);
                if (met > 0.f) {
                    int slot = atomicAdd(&sP[wid], 1);
                    if (slot < CAP) {
                        skey[wid][slot] = ((unsigned long long)__float_as_uint(met) << 32)
                                        | (unsigned)(0xFFFFFFFFu - (unsigned)a);
                        sov[wid][slot] = ov;
                    }
                }
            }
        }
    }
    __syncwarp();
    int P = min(sP[wid], CAP);
    int nsel = min(P, TOPK);

    // warp-only top-k: 13 rounds of shfl max-reduction, no block barriers
    for (int r = 0; r < nsel; r++) {
        unsigned long long best = 0; int bslot = -1;
        for (int i = lane; i < P; i += 32)
            if (skey[wid][i] > best) { best = skey[wid][i]; bslot = i; }
        #pragma unroll
        for (int off = 16; off > 0; off >>= 1) {
            unsigned long long ob = __shfl_down_sync(0xFFFFFFFFu, best, off);
            int os = __shfl_down_sync(0xFFFFFFFFu, bslot, off);
            if (ob > best) { best = ob; bslot = os; }
        }
        if (lane == 0) {
            sfidx[wid][r] = (int)(0xFFFFFFFFu - (unsigned)(best & 0xFFFFFFFFull));
            sfmet[wid][r] = __uint_as_float((unsigned)(best >> 32));
            sfovl[wid][r] = sov[wid][bslot];
            skey[wid][bslot] = 0ull;
        }
        __syncwarp();
    }

    int kfill = nsel;
    if (nsel < TOPK) {
        if (lane == 0) {
            // top_k fills remaining slots with smallest-index zero-metric anchors;
            // they survive only if inside the gt box.
            int slots = nsel;
            int a = 0;
            while (slots < TOPK && a < NA) {
                bool ispos = false;
                for (int t = 0; t < nsel; t++)
                    if (sfidx[wid][t] == a) { ispos = true; break; }
                if (!ispos) {
                    slots++;
                    float ax = anc[a * 2 + 0], ay = anc[a * 2 + 1];
                    if (ax - gx1 > EPSF && ay - gy1 > EPSF && gx2 - ax > EPSF && gy2 - ay > EPSF) {
                        sfidx[wid][kfill] = a; sfmet[wid][kfill] = 0.f; sfovl[wid][kfill] = 0.f;
                        kfill++;
                    }
                }
                a++;
            }
        }
        kfill = __shfl_sync(0xFFFFFFFFu, kfill, 0);
    }
    __syncwarp();

    if (lane < kfill) {
        int a = sfidx[wid][lane];
        int pos = b * NA + a;
        int old = atomicAdd(&g_cnt[pos], 1);
        if (old == 0) {
            int t = atomicAdd(&g_s.ntouch, 1);
            g_touch[t] = pos;
        }
        g_candj[pos] = j;            // race only matters when cnt>1 (value unused then)
        g_met_a[pos] = sfmet[wid][lane];
        g_ov_a[pos]  = sfovl[wid][lane];
    }
}

// ---------------- kernel C: per-touched-anchor resolution + pos maxima (+ cnt reset) ----------------
__global__ void k_resolve(const float* __restrict__ pd_scores, const int* __restrict__ gt_labels) {
    int i = blockIdx.x * blockDim.x + threadIdx.x;
    if (i >= g_s.ntouch) return;
    int pos = g_touch[i];
    int c = g_cnt[pos];
    g_cnt[pos] = 0;                  // restore all-zero invariant (touched-only dirty)
    int b = pos / NA;
    int jm; float met, ov;
    if (c == 1) {
        jm = g_candj[pos]; met = g_met_a[pos]; ov = g_ov_a[pos];
    } else {
        // overlaps argmax precomputed during the candidate scan
        unsigned long long key = g_s.ovkey[pos];
        if (key == 0ull) {           // no gt had ov>0 for this anchor: argmax of zero row = 0
            jm = 0; ov = 0.f;
        } else {
            jm = NB - 1 - (int)(key & 0xFFFFFFFFull);
            ov = __uint_as_float((unsigned)(key >> 32));
        }
        met = (ov > 0.f)
            ? __ldg(pd_scores + (long long)pos * NC + __ldg(gt_labels + b * NB + jm)) * pow6(ov)
            : 0.f;
    }
    g_assigned[pos] = jm + 1;        // 0 = background encoding
    g_norm_al[pos]  = met;
    atomicMax(&g_s.pos_align[b * NB + jm], __float_as_uint(met));
    atomicMax(&g_s.pos_over [b * NB + jm], __float_as_uint(ov));
}

// ---------------- kernel D: metadata outputs + sparse one-hot (scores pre-zeroed by k_rows) ----------------
__global__ void k_out(const int* __restrict__ gt_labels, const float* __restrict__ gt_bboxes,
                      float* __restrict__ out) {
    int b = blockIdx.y;
    int a = blockIdx.x * blockDim.x + threadIdx.x;
    if (a >= NA) return;
    const long long L = (long long)BS * NA;
    long long pos = (long long)b * NA + a;
    int v = g_assigned[pos];
    bool fg = (v > 0);
    if (fg) g_assigned[pos] = 0;     // restore all-zero invariant (touched-only dirty)
    int jm = v - 1;
    int j0 = fg ? jm : 0;
    int label = gt_labels[b * NB + j0];
    const float4 gb = *(const float4*)(gt_bboxes + (b * NB + j0) * 4);
    out[pos] = (float)label;
    *(float4*)(out + L + pos * 4) = gb;
    out[L * 5 + L * NC + pos] = fg ? 1.f : 0.f;
    out[L * 6 + L * NC + pos] = (float)j0;
    if (fg) {
        float pa = __uint_as_float(g_s.pos_align[b * NB + jm]);
        float po = __uint_as_float(g_s.pos_over [b * NB + jm]);
        out[L * 5 + pos * NC + label] = g_norm_al[pos] * po / (pa + EPSF);
    }
}

// ---------------- launch ----------------
extern "C" void kernel_launch(void* const* d_in, const int* in_sizes, int n_in,
                              void* d_out, int out_size) {
    const float* pd_scores = (const float*)d_in[0];
    const float* pd_bboxes = (const float*)d_in[1];
    const float* anc       = (const float*)d_in[2];
    const int*   gt_labels = (const int*)  d_in[3];
    const float* gt_bboxes = (const float*)d_in[4];
    const float* mask_gt   = (const float*)d_in[5];
    float* out = (float*)d_out;

    k_init<<<264, 1024>>>(anc);
    k_rows<<<RB_GRID + FILL_GRID, 32 * ROWS_PER_BLOCK>>>(pd_scores, pd_bboxes, anc, gt_labels, gt_bboxes, mask_gt, out);
    k_resolve<<<(TOUCH_MAX + 255) / 256, 256>>>(pd_scores, gt_labels);
    dim3 gridD((NA + 255) / 256, BS);
    k_out<<<gridD, 256>>>(gt_labels, gt_bboxes, out);
}